// round 8
// baseline (speedup 1.0000x reference)
#include <cuda_runtime.h>
#include <cuda_fp16.h>
#include <cstdint>

// ---------------- problem constants ----------------
#define NTOK 32768
#define DIN  512
#define DFF  1024
#define DFFC 512
#define NT   8
#define MAXTILES 140     // tiles of 256 tokens: <= 128 full + 7 partial

#define KT  64           // K-tile in halves
#define RSA 72           // A smem row stride (halves)
#define RSB 136          // B smem row stride (halves)
#define MT  256          // CTA M-tile rows
#define STA (MT * RSA)   // halves per A stage  (18432)
#define STB (64 * RSB)   // halves per B stage  (8704)
#define SMEM_DYN (2 * (STA + STB) * 2)   // 108544 bytes -> 1 CTA/SM (regs bind anyway)

// ---------------- device scratch ----------------
__device__ __half g_xh  [NTOK * DIN];        // x fp16
__device__ __half g_wpre[DIN * DFF];         // W_pre fp16 (natural [k][n])
__device__ __half g_wtyp[NT * DFF * DIN];    // W_types fp16 (natural [t][k][n])
__device__ __half g_wc1 [DIN * DFFC];        // W_c1 fp16 (natural [k][n])
__device__ __half g_mid [NTOK * DFF];        // relu(x @ W_pre)
__device__ __half g_xnew[NTOK * DIN];        // x + relu(mid @ Wt)
__device__ float  g_part[NTOK * 4];          // per-N-slice partial dots
__device__ int    g_perm[NTOK];
__device__ int    g_cnt[NT], g_cursor[NT];

// ---------------- helpers ----------------
static __device__ __forceinline__ uint32_t smem_u32(const void* p) {
    uint32_t a;
    asm("{ .reg .u64 t; cvta.to.shared.u64 t, %1; cvt.u32.u64 %0, t; }" : "=r"(a) : "l"(p));
    return a;
}
static __device__ __forceinline__ void cpasync16(uint32_t s, const void* g) {
    asm volatile("cp.async.cg.shared.global [%0], [%1], 16;" :: "r"(s), "l"(g));
}
#define CP_COMMIT() asm volatile("cp.async.commit_group;" ::: "memory")
#define CP_WAIT1()  asm volatile("cp.async.wait_group 1;" ::: "memory")

static __device__ __forceinline__ void ldsm4(uint32_t* r, uint32_t a) {
    asm volatile("ldmatrix.sync.aligned.m8n8.x4.shared.b16 {%0,%1,%2,%3}, [%4];"
                 : "=r"(r[0]), "=r"(r[1]), "=r"(r[2]), "=r"(r[3]) : "r"(a));
}
static __device__ __forceinline__ void ldsm4t(uint32_t* r, uint32_t a) {
    asm volatile("ldmatrix.sync.aligned.m8n8.x4.trans.shared.b16 {%0,%1,%2,%3}, [%4];"
                 : "=r"(r[0]), "=r"(r[1]), "=r"(r[2]), "=r"(r[3]) : "r"(a));
}
static __device__ __forceinline__ void mma16816(float* d, const uint32_t* a, const uint32_t* b) {
    asm volatile("mma.sync.aligned.m16n8k16.row.col.f32.f16.f16.f32 "
                 "{%0,%1,%2,%3}, {%4,%5,%6,%7}, {%8,%9}, {%0,%1,%2,%3};"
                 : "+f"(d[0]), "+f"(d[1]), "+f"(d[2]), "+f"(d[3])
                 : "r"(a[0]), "r"(a[1]), "r"(a[2]), "r"(a[3]), "r"(b[0]), "r"(b[1]));
}

// ---------------- prep: fp32 -> fp16 converts + histogram ----------------
__global__ void prep_kernel(const float* __restrict__ x, const float* __restrict__ wp,
                            const float* __restrict__ wt, const float* __restrict__ wc,
                            const int* __restrict__ tr) {
    __shared__ int cnt[NT];
    __shared__ int det;
    int tid = threadIdx.x;
    int g = blockIdx.x * blockDim.x + tid;
    int nth = gridDim.x * blockDim.x;
    if (g < NT) { g_cnt[g] = 0; g_cursor[g] = 0; }

    if (blockIdx.x < 128) {
        if (tid < NT) cnt[tid] = 0;
        if (tid == 0) det = 0;
        __syncthreads();
        // dtype sniff: int64 (LE) => odd int32 words are all zero (types < 8)
        if (tr[2 * tid + 1]) atomicOr(&det, 1);
        __syncthreads();
        int stride = det ? 1 : 2;
        int i = blockIdx.x * 256 + tid;
        atomicAdd(&cnt[tr[i * stride] & 7], 1);
        __syncthreads();
        if (tid < NT) atomicAdd(&g_cnt[tid], cnt[tid]);
    }

    for (int i = g; i < NTOK * DIN / 4; i += nth) {
        float4 v = ((const float4*)x)[i];
        ((__half2*)g_xh)[2 * i]     = __floats2half2_rn(v.x, v.y);
        ((__half2*)g_xh)[2 * i + 1] = __floats2half2_rn(v.z, v.w);
    }
    for (int i = g; i < DIN * DFF / 4; i += nth) {
        float4 v = ((const float4*)wp)[i];
        ((__half2*)g_wpre)[2 * i]     = __floats2half2_rn(v.x, v.y);
        ((__half2*)g_wpre)[2 * i + 1] = __floats2half2_rn(v.z, v.w);
    }
    for (int i = g; i < NT * DFF * DIN / 4; i += nth) {
        float4 v = ((const float4*)wt)[i];
        ((__half2*)g_wtyp)[2 * i]     = __floats2half2_rn(v.x, v.y);
        ((__half2*)g_wtyp)[2 * i + 1] = __floats2half2_rn(v.z, v.w);
    }
    for (int i = g; i < DIN * DFFC / 4; i += nth) {
        float4 v = ((const float4*)wc)[i];
        ((__half2*)g_wc1)[2 * i]     = __floats2half2_rn(v.x, v.y);
        ((__half2*)g_wc1)[2 * i + 1] = __floats2half2_rn(v.z, v.w);
    }
}

__global__ void scatter_kernel(const int* __restrict__ tr) {  // grid 128 x 256
    __shared__ int cnt[NT], base[NT];
    __shared__ int det;
    int tid = threadIdx.x;
    if (tid < NT) cnt[tid] = 0;
    if (tid == 0) det = 0;
    __syncthreads();
    if (tr[2 * tid + 1]) atomicOr(&det, 1);
    __syncthreads();
    int stride = det ? 1 : 2;
    int i = blockIdx.x * 256 + tid;
    int t = tr[i * stride] & 7;
    int ls = atomicAdd(&cnt[t], 1);
    __syncthreads();
    if (tid < NT) {
        int pre = 0;
#pragma unroll
        for (int j = 0; j < NT; j++) if (j < tid) pre += g_cnt[j];
        base[tid] = pre + atomicAdd(&g_cursor[tid], cnt[tid]);
    }
    __syncthreads();
    g_perm[base[t] + ls] = i;
}

// ---------------- unified 256x128 tile GEMM, 8 warps of 64x64, 2-stage ----------------
// MODE 0: mid  = relu(xh @ wpre)            NK=8,  N=1024
// MODE 1: xnew = x + relu(mid_g @ wtyp[t])  NK=16, N=512, gathered rows (in-kernel plan)
// MODE 2: part = (relu(xnew @ wc1) . wc2)   NK=8,  N=512, fused GEMV
template<int MODE, int NK>
__global__ void __launch_bounds__(256, 1) gemm_kernel(const float* __restrict__ x,
                                                      const float* __restrict__ wc2) {
    extern __shared__ __half smem[];
    __half* smA = smem;             // [2][STA]
    __half* smB = smem + 2 * STA;   // [2][STB]
    __shared__ int tok[MT];
    __shared__ float red[2 * MT];
    __shared__ float swc2[DFFC];

    int tid = threadIdx.x, lane = tid & 31, wid = tid >> 5;
    int wm = wid >> 1, wn = wid & 1;          // 4 x 2 warp grid -> 256 x 128
    int n0 = blockIdx.x * 128;
    int m0 = 0, cnt = MT;

    const __half* Asrc;
    const __half* Bsrc;
    int lda, ldb;
    if (MODE == 0) {
        Asrc = g_xh;  lda = DIN;  Bsrc = g_wpre; ldb = DFF;  m0 = blockIdx.y * MT;
    } else if (MODE == 1) {
        // in-kernel tile plan from g_cnt (all threads redundantly), tiles of 256
        int tile = blockIdx.y;
        int nt = 0, off = 0, t = -1, st0 = 0;
#pragma unroll
        for (int i = 0; i < NT; i++) {
            int ci = g_cnt[i];
            int nti = (ci + MT - 1) >> 8;
            if (t < 0 && tile < nt + nti) {
                int j = tile - nt;
                t = i; st0 = off + j * MT; cnt = min(MT, ci - j * MT);
            }
            nt += nti; off += ci;
        }
        if (t < 0) return;
        tok[tid] = g_perm[st0 + min(tid, cnt - 1)];
        Asrc = g_mid; lda = DFF;  Bsrc = g_wtyp + (size_t)t * DFF * DIN; ldb = DIN;
        __syncthreads();
    } else {
        Asrc = g_xnew; lda = DIN; Bsrc = g_wc1; ldb = DFFC; m0 = blockIdx.y * MT;
        for (int i = tid; i < DFFC; i += 256) swc2[i] = wc2[i];
    }

    uint32_t sA = smem_u32(smA), sB = smem_u32(smB);

    auto loadA = [&](int stg, int kt) {
#pragma unroll
        for (int i = tid; i < MT * 8; i += 256) {   // 256 rows x 8 chunks(16B)
            int r = i >> 3, c = i & 7;
            int row = (MODE == 1) ? tok[r] : (m0 + r);
            cpasync16(sA + (uint32_t)(stg * STA + r * RSA + c * 8) * 2,
                      Asrc + (size_t)row * lda + kt * KT + c * 8);
        }
    };
    auto loadB = [&](int stg, int kt) {
#pragma unroll
        for (int i = tid; i < 1024; i += 256) {   // 64 k-rows x 16 chunks(16B)
            int r = i >> 4, c = i & 15;
            cpasync16(sB + (uint32_t)(stg * STB + r * RSB + c * 8) * 2,
                      Bsrc + (size_t)(kt * KT + r) * ldb + n0 + c * 8);
        }
    };

    float acc[4][8][4];
#pragma unroll
    for (int mi = 0; mi < 4; mi++)
#pragma unroll
        for (int ni = 0; ni < 8; ni++)
#pragma unroll
            for (int e = 0; e < 4; e++) acc[mi][ni][e] = 0.f;

    loadA(0, 0); loadB(0, 0); CP_COMMIT();
    loadA(1, 1); loadB(1, 1); CP_COMMIT();

    for (int kt = 0; kt < NK; kt++) {
        CP_WAIT1();
        __syncthreads();
        int st = kt & 1;
        uint32_t aB = sA + (uint32_t)(st * STA) * 2;
        uint32_t bB = sB + (uint32_t)(st * STB) * 2;
#pragma unroll
        for (int ks = 0; ks < 4; ks++) {
            uint32_t af[4][4], bf[8][2];
#pragma unroll
            for (int mi = 0; mi < 4; mi++) {
                int row = wm * 64 + mi * 16 + (lane & 15);
                ldsm4(af[mi], aB + (uint32_t)(row * RSA + ks * 16 + ((lane >> 4) << 3)) * 2);
            }
#pragma unroll
            for (int nb = 0; nb < 4; nb++) {
                uint32_t t4[4];
                int row = ks * 16 + (lane & 15);
                int colh = wn * 64 + nb * 16 + ((lane >> 4) << 3);
                ldsm4t(t4, bB + (uint32_t)(row * RSB + colh) * 2);
                bf[nb * 2][0] = t4[0];     bf[nb * 2][1] = t4[1];
                bf[nb * 2 + 1][0] = t4[2]; bf[nb * 2 + 1][1] = t4[3];
            }
#pragma unroll
            for (int mi = 0; mi < 4; mi++)
#pragma unroll
                for (int ni = 0; ni < 8; ni++)
                    mma16816(acc[mi][ni], af[mi], bf[ni]);
        }
        __syncthreads();
        if (kt + 2 < NK) { loadA(st, kt + 2); loadB(st, kt + 2); }
        CP_COMMIT();
    }

    // ---- epilogues ----
    if (MODE == 2) {
#pragma unroll
        for (int mi = 0; mi < 4; mi++) {
#pragma unroll
            for (int hf = 0; hf < 2; hf++) {
                float p = 0.f;
#pragma unroll
                for (int ni = 0; ni < 8; ni++) {
                    int col = n0 + wn * 64 + ni * 8 + 2 * (lane & 3);
                    p += fmaxf(acc[mi][ni][hf * 2], 0.f) * swc2[col]
                       + fmaxf(acc[mi][ni][hf * 2 + 1], 0.f) * swc2[col + 1];
                }
                p += __shfl_xor_sync(0xFFFFFFFFu, p, 1);
                p += __shfl_xor_sync(0xFFFFFFFFu, p, 2);
                if ((lane & 3) == 0)
                    red[wn * MT + wm * 64 + mi * 16 + hf * 8 + (lane >> 2)] = p;
            }
        }
        __syncthreads();
        g_part[(size_t)(m0 + tid) * 4 + blockIdx.x] = red[tid] + red[MT + tid];
    } else {
#pragma unroll
        for (int mi = 0; mi < 4; mi++) {
#pragma unroll
            for (int hf = 0; hf < 2; hf++) {
                int lr = wm * 64 + mi * 16 + (lane >> 2) + hf * 8;
#pragma unroll
                for (int ni = 0; ni < 8; ni++) {
                    float d0 = acc[mi][ni][hf * 2], d1 = acc[mi][ni][hf * 2 + 1];
                    int col = n0 + wn * 64 + ni * 8 + 2 * (lane & 3);
                    if (MODE == 0) {
                        __half2 v = __floats2half2_rn(fmaxf(d0, 0.f), fmaxf(d1, 0.f));
                        *(__half2*)(g_mid + (size_t)(m0 + lr) * DFF + col) = v;
                    } else {
                        if (lr < cnt) {
                            int tk = tok[lr];
                            float2 xv = *(const float2*)(x + (size_t)tk * DIN + col);
                            __half2 v = __floats2half2_rn(xv.x + fmaxf(d0, 0.f),
                                                          xv.y + fmaxf(d1, 0.f));
                            *(__half2*)(g_xnew + (size_t)tk * DIN + col) = v;
                        }
                    }
                }
            }
        }
    }
}

// ---------------- final deterministic 4-way sum ----------------
__global__ void out_kernel(float* __restrict__ out) {
    int r = blockIdx.x * blockDim.x + threadIdx.x;
    float4 p = ((const float4*)g_part)[r];
    out[r] = (p.x + p.y) + (p.z + p.w);
}

// ---------------- launch ----------------
extern "C" void kernel_launch(void* const* d_in, const int* in_sizes, int n_in,
                              void* d_out, int out_size) {
    const float* x    = (const float*)d_in[0];
    const int*   typ  = (const int*)d_in[1];
    const float* Wpre = (const float*)d_in[2];
    const float* Wtyp = (const float*)d_in[3];
    const float* Wc1  = (const float*)d_in[4];
    const float* Wc2  = (const float*)d_in[5];
    float* out = (float*)d_out;

    cudaFuncSetAttribute(gemm_kernel<0, 8>,  cudaFuncAttributeMaxDynamicSharedMemorySize, SMEM_DYN);
    cudaFuncSetAttribute(gemm_kernel<1, 16>, cudaFuncAttributeMaxDynamicSharedMemorySize, SMEM_DYN);
    cudaFuncSetAttribute(gemm_kernel<2, 8>,  cudaFuncAttributeMaxDynamicSharedMemorySize, SMEM_DYN);

    prep_kernel<<<2048, 256>>>(x, Wpre, Wtyp, Wc1, typ);
    scatter_kernel<<<128, 256>>>(typ);

    gemm_kernel<0, 8><<<dim3(8, 128), 256, SMEM_DYN>>>(x, Wc2);        // mid
    gemm_kernel<1, 16><<<dim3(4, MAXTILES), 256, SMEM_DYN>>>(x, Wc2);  // routed + residual
    gemm_kernel<2, 8><<<dim3(4, 128), 256, SMEM_DYN>>>(x, Wc2);        // (relu(. @ wc1)).wc2 partials
    out_kernel<<<128, 256>>>(out);
}

// round 9
// speedup vs baseline: 1.1492x; 1.1492x over previous
#include <cuda_runtime.h>
#include <cuda_fp16.h>
#include <cstdint>

// ---------------- problem constants ----------------
#define NTOK 32768
#define DIN  512
#define DFF  1024
#define DFFC 512
#define NT   8
#define MAXTILES 264

#define KT  64           // K-tile in halves
#define RSA 72           // A smem row stride (halves)
#define RSB 136          // B smem row stride (halves)
#define STA (128 * RSA)  // halves per A stage  (9216)
#define STB (64 * RSB)   // halves per B stage  (8704)
#define SMEM_DYN (2 * (STA + STB) * 2)   // 71680 bytes -> 2 CTA/SM

// ---------------- device scratch ----------------
__device__ __half g_xh  [NTOK * DIN];        // x fp16
__device__ __half g_wpre[DIN * DFF];         // W_pre fp16 (natural [k][n])
__device__ __half g_wtyp[NT * DFF * DIN];    // W_types fp16 (natural [t][k][n])
__device__ __half g_wc1 [DIN * DFFC];        // W_c1 fp16 (natural [k][n])
__device__ __half g_mid [NTOK * DFF];        // relu(x @ W_pre)
__device__ __half g_xnew[NTOK * DIN];        // x + relu(mid @ Wt)
__device__ float  g_part[NTOK * 4];          // per-N-slice partial dots
__device__ int    g_perm[NTOK];
__device__ int    g_cnt[NT], g_cursor[NT];

// ---------------- helpers ----------------
static __device__ __forceinline__ uint32_t smem_u32(const void* p) {
    uint32_t a;
    asm("{ .reg .u64 t; cvta.to.shared.u64 t, %1; cvt.u32.u64 %0, t; }" : "=r"(a) : "l"(p));
    return a;
}
static __device__ __forceinline__ void cpasync16(uint32_t s, const void* g) {
    asm volatile("cp.async.cg.shared.global [%0], [%1], 16;" :: "r"(s), "l"(g));
}
#define CP_COMMIT() asm volatile("cp.async.commit_group;" ::: "memory")
#define CP_WAIT1()  asm volatile("cp.async.wait_group 1;" ::: "memory")

static __device__ __forceinline__ void ldsm4(uint32_t* r, uint32_t a) {
    asm volatile("ldmatrix.sync.aligned.m8n8.x4.shared.b16 {%0,%1,%2,%3}, [%4];"
                 : "=r"(r[0]), "=r"(r[1]), "=r"(r[2]), "=r"(r[3]) : "r"(a));
}
static __device__ __forceinline__ void ldsm4t(uint32_t* r, uint32_t a) {
    asm volatile("ldmatrix.sync.aligned.m8n8.x4.trans.shared.b16 {%0,%1,%2,%3}, [%4];"
                 : "=r"(r[0]), "=r"(r[1]), "=r"(r[2]), "=r"(r[3]) : "r"(a));
}
static __device__ __forceinline__ void mma16816(float* d, const uint32_t* a, const uint32_t* b) {
    asm volatile("mma.sync.aligned.m16n8k16.row.col.f32.f16.f16.f32 "
                 "{%0,%1,%2,%3}, {%4,%5,%6,%7}, {%8,%9}, {%0,%1,%2,%3};"
                 : "+f"(d[0]), "+f"(d[1]), "+f"(d[2]), "+f"(d[3])
                 : "r"(a[0]), "r"(a[1]), "r"(a[2]), "r"(a[3]), "r"(b[0]), "r"(b[1]));
}

// ---------------- prep: fp32 -> fp16 converts + histogram ----------------
__global__ void prep_kernel(const float* __restrict__ x, const float* __restrict__ wp,
                            const float* __restrict__ wt, const float* __restrict__ wc,
                            const int* __restrict__ tr) {
    __shared__ int cnt[NT];
    __shared__ int det;
    int tid = threadIdx.x;
    int g = blockIdx.x * blockDim.x + tid;
    int nth = gridDim.x * blockDim.x;
    if (g < NT) { g_cnt[g] = 0; g_cursor[g] = 0; }

    if (blockIdx.x < 128) {
        if (tid < NT) cnt[tid] = 0;
        if (tid == 0) det = 0;
        __syncthreads();
        // dtype sniff: int64 (LE) => odd int32 words are all zero (types < 8)
        if (tr[2 * tid + 1]) atomicOr(&det, 1);
        __syncthreads();
        int stride = det ? 1 : 2;
        int i = blockIdx.x * 256 + tid;
        atomicAdd(&cnt[tr[i * stride] & 7], 1);
        __syncthreads();
        if (tid < NT) atomicAdd(&g_cnt[tid], cnt[tid]);
    }

    for (int i = g; i < NTOK * DIN / 4; i += nth) {
        float4 v = ((const float4*)x)[i];
        ((__half2*)g_xh)[2 * i]     = __floats2half2_rn(v.x, v.y);
        ((__half2*)g_xh)[2 * i + 1] = __floats2half2_rn(v.z, v.w);
    }
    for (int i = g; i < DIN * DFF / 4; i += nth) {
        float4 v = ((const float4*)wp)[i];
        ((__half2*)g_wpre)[2 * i]     = __floats2half2_rn(v.x, v.y);
        ((__half2*)g_wpre)[2 * i + 1] = __floats2half2_rn(v.z, v.w);
    }
    for (int i = g; i < NT * DFF * DIN / 4; i += nth) {
        float4 v = ((const float4*)wt)[i];
        ((__half2*)g_wtyp)[2 * i]     = __floats2half2_rn(v.x, v.y);
        ((__half2*)g_wtyp)[2 * i + 1] = __floats2half2_rn(v.z, v.w);
    }
    for (int i = g; i < DIN * DFFC / 4; i += nth) {
        float4 v = ((const float4*)wc)[i];
        ((__half2*)g_wc1)[2 * i]     = __floats2half2_rn(v.x, v.y);
        ((__half2*)g_wc1)[2 * i + 1] = __floats2half2_rn(v.z, v.w);
    }
}

__global__ void scatter_kernel(const int* __restrict__ tr) {  // grid 128 x 256
    __shared__ int cnt[NT], base[NT];
    __shared__ int det;
    int tid = threadIdx.x;
    if (tid < NT) cnt[tid] = 0;
    if (tid == 0) det = 0;
    __syncthreads();
    if (tr[2 * tid + 1]) atomicOr(&det, 1);
    __syncthreads();
    int stride = det ? 1 : 2;
    int i = blockIdx.x * 256 + tid;
    int t = tr[i * stride] & 7;
    int ls = atomicAdd(&cnt[t], 1);
    __syncthreads();
    if (tid < NT) {
        int pre = 0;
#pragma unroll
        for (int j = 0; j < NT; j++) if (j < tid) pre += g_cnt[j];
        base[tid] = pre + atomicAdd(&g_cursor[tid], cnt[tid]);
    }
    __syncthreads();
    g_perm[base[t] + ls] = i;
}

// ---------------- 128x128 tile GEMM, 8 warps of 32x64, 2-stage (R7 pipeline) ----------------
// MODE 0: mid  = relu(xh @ wpre)            NK=8,  N=1024
// MODE 1: xnew = x + relu(mid_g @ wtyp[t])  NK=16, N=512, gathered rows (in-kernel plan)
// MODE 2: part = (relu(xnew @ wc1) . wc2)   NK=8,  N=512, fused GEMV
template<int MODE, int NK>
__global__ void __launch_bounds__(256, 2) gemm_kernel(const float* __restrict__ x,
                                                      const float* __restrict__ wc2) {
    extern __shared__ __half smem[];
    __half* smA = smem;             // [2][STA]
    __half* smB = smem + 2 * STA;   // [2][STB]
    __shared__ int tok[128];
    __shared__ float red[256];
    __shared__ float swc2[DFFC];

    int tid = threadIdx.x, lane = tid & 31, wid = tid >> 5;
    int wm = wid >> 1, wn = wid & 1;          // 4(m) x 2(n) warp grid, warp tile 32x64
    int n0 = blockIdx.x * 128;
    int m0 = 0, cnt = 128;

    const __half* Asrc;
    const __half* Bsrc;
    int lda, ldb;
    if (MODE == 0) {
        Asrc = g_xh;  lda = DIN;  Bsrc = g_wpre; ldb = DFF;  m0 = blockIdx.y * 128;
    } else if (MODE == 1) {
        // in-kernel tile plan from g_cnt (all threads redundantly)
        int tile = blockIdx.y;
        int nt = 0, off = 0, t = -1, st0 = 0;
#pragma unroll
        for (int i = 0; i < NT; i++) {
            int ci = g_cnt[i];
            int nti = (ci + 127) >> 7;
            if (t < 0 && tile < nt + nti) {
                int j = tile - nt;
                t = i; st0 = off + j * 128; cnt = min(128, ci - j * 128);
            }
            nt += nti; off += ci;
        }
        if (t < 0) return;
        if (tid < 128) tok[tid] = g_perm[st0 + min(tid, cnt - 1)];
        Asrc = g_mid; lda = DFF;  Bsrc = g_wtyp + (size_t)t * DFF * DIN; ldb = DIN;
        __syncthreads();
    } else {
        Asrc = g_xnew; lda = DIN; Bsrc = g_wc1; ldb = DFFC; m0 = blockIdx.y * 128;
        for (int i = tid; i < DFFC; i += 256) swc2[i] = wc2[i];
    }

    uint32_t sA = smem_u32(smA), sB = smem_u32(smB);

    auto loadA = [&](int stg, int kt) {
#pragma unroll
        for (int i = tid; i < 1024; i += 256) {   // 128 rows x 8 chunks(16B)
            int r = i >> 3, c = i & 7;
            int row = (MODE == 1) ? tok[r] : (m0 + r);
            cpasync16(sA + (uint32_t)(stg * STA + r * RSA + c * 8) * 2,
                      Asrc + (size_t)row * lda + kt * KT + c * 8);
        }
    };
    auto loadB = [&](int stg, int kt) {
#pragma unroll
        for (int i = tid; i < 1024; i += 256) {   // 64 k-rows x 16 chunks(16B)
            int r = i >> 4, c = i & 15;
            cpasync16(sB + (uint32_t)(stg * STB + r * RSB + c * 8) * 2,
                      Bsrc + (size_t)(kt * KT + r) * ldb + n0 + c * 8);
        }
    };

    float acc[2][8][4];
#pragma unroll
    for (int mi = 0; mi < 2; mi++)
#pragma unroll
        for (int ni = 0; ni < 8; ni++)
#pragma unroll
            for (int e = 0; e < 4; e++) acc[mi][ni][e] = 0.f;

    loadA(0, 0); loadB(0, 0); CP_COMMIT();
    loadA(1, 1); loadB(1, 1); CP_COMMIT();

    for (int kt = 0; kt < NK; kt++) {
        CP_WAIT1();
        __syncthreads();
        int st = kt & 1;
        uint32_t aB = sA + (uint32_t)(st * STA) * 2;
        uint32_t bB = sB + (uint32_t)(st * STB) * 2;
#pragma unroll
        for (int ks = 0; ks < 4; ks++) {
            uint32_t af[2][4], bf[8][2];
#pragma unroll
            for (int mi = 0; mi < 2; mi++) {
                int row = wm * 32 + mi * 16 + (lane & 15);
                ldsm4(af[mi], aB + (uint32_t)(row * RSA + ks * 16 + ((lane >> 4) << 3)) * 2);
            }
#pragma unroll
            for (int nb = 0; nb < 4; nb++) {
                uint32_t t4[4];
                int row = ks * 16 + (lane & 15);
                int colh = wn * 64 + nb * 16 + ((lane >> 4) << 3);
                ldsm4t(t4, bB + (uint32_t)(row * RSB + colh) * 2);
                bf[nb * 2][0] = t4[0];     bf[nb * 2][1] = t4[1];
                bf[nb * 2 + 1][0] = t4[2]; bf[nb * 2 + 1][1] = t4[3];
            }
#pragma unroll
            for (int mi = 0; mi < 2; mi++)
#pragma unroll
                for (int ni = 0; ni < 8; ni++)
                    mma16816(acc[mi][ni], af[mi], bf[ni]);
        }
        __syncthreads();
        if (kt + 2 < NK) { loadA(st, kt + 2); loadB(st, kt + 2); }
        CP_COMMIT();
    }

    // ---- epilogues ----
    if (MODE == 2) {
#pragma unroll
        for (int mi = 0; mi < 2; mi++) {
#pragma unroll
            for (int hf = 0; hf < 2; hf++) {
                float p = 0.f;
#pragma unroll
                for (int ni = 0; ni < 8; ni++) {
                    int col = n0 + wn * 64 + ni * 8 + 2 * (lane & 3);
                    p += fmaxf(acc[mi][ni][hf * 2], 0.f) * swc2[col]
                       + fmaxf(acc[mi][ni][hf * 2 + 1], 0.f) * swc2[col + 1];
                }
                p += __shfl_xor_sync(0xFFFFFFFFu, p, 1);
                p += __shfl_xor_sync(0xFFFFFFFFu, p, 2);
                if ((lane & 3) == 0)
                    red[wn * 128 + wm * 32 + mi * 16 + hf * 8 + (lane >> 2)] = p;
            }
        }
        __syncthreads();
        if (tid < 128)
            g_part[(size_t)(m0 + tid) * 4 + blockIdx.x] = red[tid] + red[128 + tid];
    } else {
#pragma unroll
        for (int mi = 0; mi < 2; mi++) {
#pragma unroll
            for (int hf = 0; hf < 2; hf++) {
                int lr = wm * 32 + mi * 16 + (lane >> 2) + hf * 8;
#pragma unroll
                for (int ni = 0; ni < 8; ni++) {
                    float d0 = acc[mi][ni][hf * 2], d1 = acc[mi][ni][hf * 2 + 1];
                    int col = n0 + wn * 64 + ni * 8 + 2 * (lane & 3);
                    if (MODE == 0) {
                        __half2 v = __floats2half2_rn(fmaxf(d0, 0.f), fmaxf(d1, 0.f));
                        *(__half2*)(g_mid + (size_t)(m0 + lr) * DFF + col) = v;
                    } else {
                        if (lr < cnt) {
                            int tk = tok[lr];
                            float2 xv = *(const float2*)(x + (size_t)tk * DIN + col);
                            __half2 v = __floats2half2_rn(xv.x + fmaxf(d0, 0.f),
                                                          xv.y + fmaxf(d1, 0.f));
                            *(__half2*)(g_xnew + (size_t)tk * DIN + col) = v;
                        }
                    }
                }
            }
        }
    }
}

// ---------------- final deterministic 4-way sum ----------------
__global__ void out_kernel(float* __restrict__ out) {
    int r = blockIdx.x * blockDim.x + threadIdx.x;
    float4 p = ((const float4*)g_part)[r];
    out[r] = (p.x + p.y) + (p.z + p.w);
}

// ---------------- launch ----------------
extern "C" void kernel_launch(void* const* d_in, const int* in_sizes, int n_in,
                              void* d_out, int out_size) {
    const float* x    = (const float*)d_in[0];
    const int*   typ  = (const int*)d_in[1];
    const float* Wpre = (const float*)d_in[2];
    const float* Wtyp = (const float*)d_in[3];
    const float* Wc1  = (const float*)d_in[4];
    const float* Wc2  = (const float*)d_in[5];
    float* out = (float*)d_out;

    cudaFuncSetAttribute(gemm_kernel<0, 8>,  cudaFuncAttributeMaxDynamicSharedMemorySize, SMEM_DYN);
    cudaFuncSetAttribute(gemm_kernel<1, 16>, cudaFuncAttributeMaxDynamicSharedMemorySize, SMEM_DYN);
    cudaFuncSetAttribute(gemm_kernel<2, 8>,  cudaFuncAttributeMaxDynamicSharedMemorySize, SMEM_DYN);

    prep_kernel<<<2048, 256>>>(x, Wpre, Wtyp, Wc1, typ);
    scatter_kernel<<<128, 256>>>(typ);

    gemm_kernel<0, 8><<<dim3(8, 256), 256, SMEM_DYN>>>(x, Wc2);        // mid
    gemm_kernel<1, 16><<<dim3(4, MAXTILES), 256, SMEM_DYN>>>(x, Wc2);  // routed + residual
    gemm_kernel<2, 8><<<dim3(4, 256), 256, SMEM_DYN>>>(x, Wc2);        // (relu(. @ wc1)).wc2 partials
    out_kernel<<<128, 256>>>(out);
}

// round 10
// speedup vs baseline: 1.1900x; 1.0355x over previous
#include <cuda_runtime.h>
#include <cuda_fp16.h>
#include <cstdint>

// ---------------- problem constants ----------------
#define NTOK 32768
#define DIN  512
#define DFF  1024
#define DFFC 512
#define NT   8
#define MAXTILES 264

#define KT  64           // K-tile in halves
#define RSA 72           // A smem row stride (halves)
#define RSB 136          // B smem row stride (halves)
#define STA (128 * RSA)  // halves per A stage  (9216)
#define STB (64 * RSB)   // halves per B stage  (8704)
#define SMEM_DYN (2 * (STA + STB) * 2)   // 71680 bytes -> 2 CTA/SM

// ---------------- device scratch ----------------
__device__ __half g_xh  [NTOK * DIN];        // x fp16
__device__ __half g_wpre[DIN * DFF];         // W_pre fp16 (natural [k][n])
__device__ __half g_wtyp[NT * DFF * DIN];    // W_types fp16 (natural [t][k][n])
__device__ __half g_wc1 [DIN * DFFC];        // W_c1 fp16 (natural [k][n])
__device__ __half g_mid [NTOK * DFF];        // relu(x @ W_pre)
__device__ __half g_xnew[NTOK * DIN];        // x + relu(mid @ Wt)
__device__ float  g_part[NTOK * 4];          // per-N-slice partial dots
__device__ int    g_perm[NTOK];
__device__ int    g_cnt[NT], g_cursor[NT];

// ---------------- helpers ----------------
static __device__ __forceinline__ uint32_t smem_u32(const void* p) {
    uint32_t a;
    asm("{ .reg .u64 t; cvta.to.shared.u64 t, %1; cvt.u32.u64 %0, t; }" : "=r"(a) : "l"(p));
    return a;
}
static __device__ __forceinline__ void cpasync16(uint32_t s, const void* g) {
    asm volatile("cp.async.cg.shared.global [%0], [%1], 16;" :: "r"(s), "l"(g));
}
#define CP_COMMIT() asm volatile("cp.async.commit_group;" ::: "memory")
#define CP_WAIT1()  asm volatile("cp.async.wait_group 1;" ::: "memory")

static __device__ __forceinline__ void ldsm4(uint32_t* r, uint32_t a) {
    asm volatile("ldmatrix.sync.aligned.m8n8.x4.shared.b16 {%0,%1,%2,%3}, [%4];"
                 : "=r"(r[0]), "=r"(r[1]), "=r"(r[2]), "=r"(r[3]) : "r"(a));
}
static __device__ __forceinline__ void ldsm4t(uint32_t* r, uint32_t a) {
    asm volatile("ldmatrix.sync.aligned.m8n8.x4.trans.shared.b16 {%0,%1,%2,%3}, [%4];"
                 : "=r"(r[0]), "=r"(r[1]), "=r"(r[2]), "=r"(r[3]) : "r"(a));
}
static __device__ __forceinline__ void mma16816(float* d, const uint32_t* a, const uint32_t* b) {
    asm volatile("mma.sync.aligned.m16n8k16.row.col.f32.f16.f16.f32 "
                 "{%0,%1,%2,%3}, {%4,%5,%6,%7}, {%8,%9}, {%0,%1,%2,%3};"
                 : "+f"(d[0]), "+f"(d[1]), "+f"(d[2]), "+f"(d[3])
                 : "r"(a[0]), "r"(a[1]), "r"(a[2]), "r"(a[3]), "r"(b[0]), "r"(b[1]));
}

// ---------------- prep: fp32 -> fp16 converts + histogram ----------------
__global__ void prep_kernel(const float* __restrict__ x, const float* __restrict__ wp,
                            const float* __restrict__ wt, const float* __restrict__ wc,
                            const int* __restrict__ tr) {
    __shared__ int cnt[NT];
    __shared__ int det;
    int tid = threadIdx.x;
    int g = blockIdx.x * blockDim.x + tid;
    int nth = gridDim.x * blockDim.x;
    if (g < NT) { g_cnt[g] = 0; g_cursor[g] = 0; }

    if (blockIdx.x < 128) {
        if (tid < NT) cnt[tid] = 0;
        if (tid == 0) det = 0;
        __syncthreads();
        // dtype sniff: int64 (LE) => odd int32 words are all zero (types < 8)
        if (tr[2 * tid + 1]) atomicOr(&det, 1);
        __syncthreads();
        int stride = det ? 1 : 2;
        int i = blockIdx.x * 256 + tid;
        atomicAdd(&cnt[tr[i * stride] & 7], 1);
        __syncthreads();
        if (tid < NT) atomicAdd(&g_cnt[tid], cnt[tid]);
    }

    for (int i = g; i < NTOK * DIN / 4; i += nth) {
        float4 v = ((const float4*)x)[i];
        ((__half2*)g_xh)[2 * i]     = __floats2half2_rn(v.x, v.y);
        ((__half2*)g_xh)[2 * i + 1] = __floats2half2_rn(v.z, v.w);
    }
    for (int i = g; i < DIN * DFF / 4; i += nth) {
        float4 v = ((const float4*)wp)[i];
        ((__half2*)g_wpre)[2 * i]     = __floats2half2_rn(v.x, v.y);
        ((__half2*)g_wpre)[2 * i + 1] = __floats2half2_rn(v.z, v.w);
    }
    for (int i = g; i < NT * DFF * DIN / 4; i += nth) {
        float4 v = ((const float4*)wt)[i];
        ((__half2*)g_wtyp)[2 * i]     = __floats2half2_rn(v.x, v.y);
        ((__half2*)g_wtyp)[2 * i + 1] = __floats2half2_rn(v.z, v.w);
    }
    for (int i = g; i < DIN * DFFC / 4; i += nth) {
        float4 v = ((const float4*)wc)[i];
        ((__half2*)g_wc1)[2 * i]     = __floats2half2_rn(v.x, v.y);
        ((__half2*)g_wc1)[2 * i + 1] = __floats2half2_rn(v.z, v.w);
    }
}

__global__ void scatter_kernel(const int* __restrict__ tr) {  // grid 128 x 256
    __shared__ int cnt[NT], base[NT];
    __shared__ int det;
    int tid = threadIdx.x;
    if (tid < NT) cnt[tid] = 0;
    if (tid == 0) det = 0;
    __syncthreads();
    if (tr[2 * tid + 1]) atomicOr(&det, 1);
    __syncthreads();
    int stride = det ? 1 : 2;
    int i = blockIdx.x * 256 + tid;
    int t = tr[i * stride] & 7;
    int ls = atomicAdd(&cnt[t], 1);
    __syncthreads();
    if (tid < NT) {
        int pre = 0;
#pragma unroll
        for (int j = 0; j < NT; j++) if (j < tid) pre += g_cnt[j];
        base[tid] = pre + atomicAdd(&g_cursor[tid], cnt[tid]);
    }
    __syncthreads();
    g_perm[base[t] + ls] = i;
}

// ---------------- 128x128 tile GEMM, 8 warps of 32x64, 2-stage, af-pipelined ----------------
// MODE 0: mid  = relu(xh @ wpre)            NK=8,  N=1024
// MODE 1: xnew = x + relu(mid_g @ wtyp[t])  NK=16, N=512, gathered rows (in-kernel plan)
// MODE 2: part = (relu(xnew @ wc1) . wc2)   NK=8,  N=512, fused GEMV
template<int MODE, int NK>
__global__ void __launch_bounds__(256, 2) gemm_kernel(const float* __restrict__ x,
                                                      const float* __restrict__ wc2) {
    extern __shared__ __half smem[];
    __half* smA = smem;             // [2][STA]
    __half* smB = smem + 2 * STA;   // [2][STB]
    __shared__ int tok[128];
    __shared__ float red[256];
    __shared__ float swc2[DFFC];

    int tid = threadIdx.x, lane = tid & 31, wid = tid >> 5;
    int wm = wid >> 1, wn = wid & 1;          // 4(m) x 2(n) warp grid, warp tile 32x64
    int n0 = blockIdx.x * 128;
    int m0 = 0, cnt = 128;

    const __half* Asrc;
    const __half* Bsrc;
    int lda, ldb;
    if (MODE == 0) {
        Asrc = g_xh;  lda = DIN;  Bsrc = g_wpre; ldb = DFF;  m0 = blockIdx.y * 128;
    } else if (MODE == 1) {
        // in-kernel tile plan from g_cnt (all threads redundantly)
        int tile = blockIdx.y;
        int nt = 0, off = 0, t = -1, st0 = 0;
#pragma unroll
        for (int i = 0; i < NT; i++) {
            int ci = g_cnt[i];
            int nti = (ci + 127) >> 7;
            if (t < 0 && tile < nt + nti) {
                int j = tile - nt;
                t = i; st0 = off + j * 128; cnt = min(128, ci - j * 128);
            }
            nt += nti; off += ci;
        }
        if (t < 0) return;
        if (tid < 128) tok[tid] = g_perm[st0 + min(tid, cnt - 1)];
        Asrc = g_mid; lda = DFF;  Bsrc = g_wtyp + (size_t)t * DFF * DIN; ldb = DIN;
        __syncthreads();
    } else {
        Asrc = g_xnew; lda = DIN; Bsrc = g_wc1; ldb = DFFC; m0 = blockIdx.y * 128;
        for (int i = tid; i < DFFC; i += 256) swc2[i] = wc2[i];
    }

    uint32_t sA = smem_u32(smA), sB = smem_u32(smB);

    auto loadA = [&](int stg, int kt) {
#pragma unroll
        for (int i = tid; i < 1024; i += 256) {   // 128 rows x 8 chunks(16B)
            int r = i >> 3, c = i & 7;
            int row = (MODE == 1) ? tok[r] : (m0 + r);
            cpasync16(sA + (uint32_t)(stg * STA + r * RSA + c * 8) * 2,
                      Asrc + (size_t)row * lda + kt * KT + c * 8);
        }
    };
    auto loadB = [&](int stg, int kt) {
#pragma unroll
        for (int i = tid; i < 1024; i += 256) {   // 64 k-rows x 16 chunks(16B)
            int r = i >> 4, c = i & 15;
            cpasync16(sB + (uint32_t)(stg * STB + r * RSB + c * 8) * 2,
                      Bsrc + (size_t)(kt * KT + r) * ldb + n0 + c * 8);
        }
    };

    float acc[2][8][4];
#pragma unroll
    for (int mi = 0; mi < 2; mi++)
#pragma unroll
        for (int ni = 0; ni < 8; ni++)
#pragma unroll
            for (int e = 0; e < 4; e++) acc[mi][ni][e] = 0.f;

    loadA(0, 0); loadB(0, 0); CP_COMMIT();
    loadA(1, 1); loadB(1, 1); CP_COMMIT();

    // A-fragment addresses: per-warp bases; af double-buffered on ks parity.
    int arow0 = wm * 32 + (lane & 15);
    uint32_t acol = (uint32_t)((lane >> 4) << 3) * 2;
    int brow = lane & 15;
    uint32_t bcolh = (uint32_t)(wn * 64 + ((lane >> 4) << 3)) * 2;

    for (int kt = 0; kt < NK; kt++) {
        CP_WAIT1();
        __syncthreads();
        int st = kt & 1;
        uint32_t aB = sA + (uint32_t)(st * STA) * 2;
        uint32_t bB = sB + (uint32_t)(st * STB) * 2;

        uint32_t af[2][2][4];   // [ks&1][mi][4]
        // preload af for ks=0
#pragma unroll
        for (int mi = 0; mi < 2; mi++)
            ldsm4(af[0][mi], aB + (uint32_t)((arow0 + mi * 16) * RSA) * 2 + acol);

#pragma unroll
        for (int ks = 0; ks < 4; ks++) {
            // prefetch af for next ks while this ks computes
            if (ks < 3) {
#pragma unroll
                for (int mi = 0; mi < 2; mi++)
                    ldsm4(af[(ks + 1) & 1][mi],
                          aB + (uint32_t)((arow0 + mi * 16) * RSA + (ks + 1) * 16) * 2 + acol);
            }
            uint32_t bRow = bB + (uint32_t)((ks * 16 + brow) * RSB) * 2 + bcolh;
#pragma unroll
            for (int nb = 0; nb < 4; nb++) {
                uint32_t t4[4];
                ldsm4t(t4, bRow + (uint32_t)(nb * 16) * 2);
#pragma unroll
                for (int mi = 0; mi < 2; mi++) {
                    mma16816(acc[mi][nb * 2],     af[ks & 1][mi], t4);      // {t4[0],t4[1]}
                    mma16816(acc[mi][nb * 2 + 1], af[ks & 1][mi], t4 + 2); // {t4[2],t4[3]}
                }
            }
        }
        __syncthreads();
        if (kt + 2 < NK) { loadA(st, kt + 2); loadB(st, kt + 2); }
        CP_COMMIT();
    }

    // ---- epilogues ----
    if (MODE == 2) {
#pragma unroll
        for (int mi = 0; mi < 2; mi++) {
#pragma unroll
            for (int hf = 0; hf < 2; hf++) {
                float p = 0.f;
#pragma unroll
                for (int ni = 0; ni < 8; ni++) {
                    int col = n0 + wn * 64 + ni * 8 + 2 * (lane & 3);
                    p += fmaxf(acc[mi][ni][hf * 2], 0.f) * swc2[col]
                       + fmaxf(acc[mi][ni][hf * 2 + 1], 0.f) * swc2[col + 1];
                }
                p += __shfl_xor_sync(0xFFFFFFFFu, p, 1);
                p += __shfl_xor_sync(0xFFFFFFFFu, p, 2);
                if ((lane & 3) == 0)
                    red[wn * 128 + wm * 32 + mi * 16 + hf * 8 + (lane >> 2)] = p;
            }
        }
        __syncthreads();
        if (tid < 128)
            g_part[(size_t)(m0 + tid) * 4 + blockIdx.x] = red[tid] + red[128 + tid];
    } else {
#pragma unroll
        for (int mi = 0; mi < 2; mi++) {
#pragma unroll
            for (int hf = 0; hf < 2; hf++) {
                int lr = wm * 32 + mi * 16 + (lane >> 2) + hf * 8;
#pragma unroll
                for (int ni = 0; ni < 8; ni++) {
                    float d0 = acc[mi][ni][hf * 2], d1 = acc[mi][ni][hf * 2 + 1];
                    int col = n0 + wn * 64 + ni * 8 + 2 * (lane & 3);
                    if (MODE == 0) {
                        __half2 v = __floats2half2_rn(fmaxf(d0, 0.f), fmaxf(d1, 0.f));
                        *(__half2*)(g_mid + (size_t)(m0 + lr) * DFF + col) = v;
                    } else {
                        if (lr < cnt) {
                            int tk = tok[lr];
                            float2 xv = *(const float2*)(x + (size_t)tk * DIN + col);
                            __half2 v = __floats2half2_rn(xv.x + fmaxf(d0, 0.f),
                                                          xv.y + fmaxf(d1, 0.f));
                            *(__half2*)(g_xnew + (size_t)tk * DIN + col) = v;
                        }
                    }
                }
            }
        }
    }
}

// ---------------- final deterministic 4-way sum ----------------
__global__ void out_kernel(float* __restrict__ out) {
    int r = blockIdx.x * blockDim.x + threadIdx.x;
    float4 p = ((const float4*)g_part)[r];
    out[r] = (p.x + p.y) + (p.z + p.w);
}

// ---------------- launch ----------------
extern "C" void kernel_launch(void* const* d_in, const int* in_sizes, int n_in,
                              void* d_out, int out_size) {
    const float* x    = (const float*)d_in[0];
    const int*   typ  = (const int*)d_in[1];
    const float* Wpre = (const float*)d_in[2];
    const float* Wtyp = (const float*)d_in[3];
    const float* Wc1  = (const float*)d_in[4];
    const float* Wc2  = (const float*)d_in[5];
    float* out = (float*)d_out;

    cudaFuncSetAttribute(gemm_kernel<0, 8>,  cudaFuncAttributeMaxDynamicSharedMemorySize, SMEM_DYN);
    cudaFuncSetAttribute(gemm_kernel<1, 16>, cudaFuncAttributeMaxDynamicSharedMemorySize, SMEM_DYN);
    cudaFuncSetAttribute(gemm_kernel<2, 8>,  cudaFuncAttributeMaxDynamicSharedMemorySize, SMEM_DYN);

    prep_kernel<<<2048, 256>>>(x, Wpre, Wtyp, Wc1, typ);
    scatter_kernel<<<128, 256>>>(typ);

    gemm_kernel<0, 8><<<dim3(8, 256), 256, SMEM_DYN>>>(x, Wc2);        // mid
    gemm_kernel<1, 16><<<dim3(4, MAXTILES), 256, SMEM_DYN>>>(x, Wc2);  // routed + residual
    gemm_kernel<2, 8><<<dim3(4, 256), 256, SMEM_DYN>>>(x, Wc2);        // (relu(. @ wc1)).wc2 partials
    out_kernel<<<128, 256>>>(out);
}